// round 2
// baseline (speedup 1.0000x reference)
#include <cuda_runtime.h>
#include <cuda_bf16.h>

#define NDIM 128
#define BLK  512

// ---------- packed f32x2 helpers (sm_103a; FFMA2 only reachable via PTX) ----------
__device__ __forceinline__ unsigned long long pack2(float lo, float hi) {
    unsigned long long r;
    asm("mov.b64 %0, {%1, %2};" : "=l"(r) : "f"(lo), "f"(hi));
    return r;
}
__device__ __forceinline__ void fma2(unsigned long long& d, unsigned long long a, unsigned long long b) {
    asm("fma.rn.f32x2 %0, %1, %2, %0;" : "+l"(d) : "l"(a), "l"(b));
}
__device__ __forceinline__ float2 unpack2(unsigned long long v) {
    float2 r;
    asm("mov.b64 {%0, %1}, %2;" : "=f"(r.x), "=f"(r.y) : "l"(v));
    return r;
}

// ---------- 128x128x128 GEMM microkernel: C = A * B (optionally relu) ----------
// 512 threads: 16 thread-rows x 32 thread-cols; each thread computes an 8x4 tile.
// A reads are warp-broadcast LDS.128 (all lanes of a warp share trow);
// B reads are conflict-free 128-bit row loads (LDS.128 or LDG.128 for global W).
template<bool RELU>
__device__ __forceinline__ void gemm128(const float* __restrict__ As,
                                        const float* __restrict__ Bs,
                                        float* __restrict__ Cs, int tid)
{
    const int tc = (tid & 31) << 2;   // column base (0..124)
    const int tr = (tid >> 5) << 3;   // row base    (0..120)

    unsigned long long acc[8][2];
#pragma unroll
    for (int r = 0; r < 8; ++r) { acc[r][0] = 0ull; acc[r][1] = 0ull; }

#pragma unroll 2
    for (int k = 0; k < NDIM; k += 4) {
        float4 a[8];
#pragma unroll
        for (int r = 0; r < 8; ++r)
            a[r] = *(const float4*)(As + (tr + r) * NDIM + k);
#pragma unroll
        for (int kk = 0; kk < 4; ++kk) {
            const ulonglong2 bv = *(const ulonglong2*)(Bs + (k + kk) * NDIM + tc);
#pragma unroll
            for (int r = 0; r < 8; ++r) {
                const float av = ((const float*)&a[r])[kk];
                const unsigned long long a2 = pack2(av, av);
                fma2(acc[r][0], a2, bv.x);
                fma2(acc[r][1], a2, bv.y);
            }
        }
    }

#pragma unroll
    for (int r = 0; r < 8; ++r) {
        float2 c01 = unpack2(acc[r][0]);
        float2 c23 = unpack2(acc[r][1]);
        float4 v = make_float4(c01.x, c01.y, c23.x, c23.y);
        if (RELU) {
            v.x = fmaxf(v.x, 0.f); v.y = fmaxf(v.y, 0.f);
            v.z = fmaxf(v.z, 0.f); v.w = fmaxf(v.w, 0.f);
        }
        *(float4*)(Cs + (tr + r) * NDIM + tc) = v;
    }
}

// ---------- persistent per-batch kernel ----------
// smem: A[128*128] | X[128*128] | Z[128*128] | prob[128] | dinv[128]  = 197632 B
__global__ void __launch_bounds__(BLK, 1)
gcn_kernel(const float* __restrict__ xg, const float* __restrict__ Wg,
           float* __restrict__ outg)
{
    extern __shared__ float smem[];
    float* A    = smem;
    float* X    = smem + 16384;
    float* Z    = smem + 32768;
    float* prob = smem + 49152;
    float* dinv = prob + NDIM;

    const int tid = threadIdx.x;
    const int b = blockIdx.x;
    const float* __restrict__ xb = xg + (size_t)b * 16384;
    float* __restrict__ ob = outg + (size_t)b * 16384;

    // ---- init: Z <- x, A <- I, out <- I ----
    for (int idx = tid; idx < 4096; idx += BLK) {
        float4 v = ((const float4*)xb)[idx];
        ((float4*)Z)[idx] = v;
        const int lin = idx << 2;
        const int r = lin >> 7, c = lin & 127;
        float4 e = make_float4(0.f, 0.f, 0.f, 0.f);
        const int d = r - c;
        if (d >= 0 && d < 4) ((float*)&e)[d] = 1.0f;
        ((float4*)A)[idx] = e;
        ((float4*)ob)[idx] = e;
    }
    __syncthreads();

    // X = relu(x @ W)
    gemm128<true>(Z, Wg, X, tid);
    __syncthreads();

    for (int i = 1; i < NDIM; ++i) {
        // ---- prob[j] = dot(X[j], X[i])  (4 threads per j) ----
        {
            const int j = tid >> 2, p = tid & 3;
            const float4* xj = (const float4*)(X + j * NDIM) + (p << 3);
            const float4* xi = (const float4*)(X + i * NDIM) + (p << 3);
            float s = 0.f;
#pragma unroll
            for (int q = 0; q < 8; ++q) {
                const float4 u = xj[q], w = xi[q];
                s += u.x * w.x + u.y * w.y + u.z * w.z + u.w * w.w;
            }
            s += __shfl_down_sync(0xffffffffu, s, 1);
            s += __shfl_down_sync(0xffffffffu, s, 2);
            if (p == 0) prob[j] = s;
        }
        // ---- Z = X @ W (independent of prob; shares the same sync) ----
        gemm128<false>(X, Wg, Z, tid);
        __syncthreads();

        // ---- splice prob into A row/col i and final output ----
        if (tid < i) {
            const float pv = prob[tid];
            A[i * NDIM + tid] = pv;
            A[tid * NDIM + i] = pv;
            ob[i * NDIM + tid] = pv;
            ob[tid * NDIM + i] = pv;
        }
        __syncthreads();

        // ---- deg -> dinv = deg^{-1/2} ----
        {
            const int j = tid >> 2, p = tid & 3;
            const float4* ar = (const float4*)(A + j * NDIM) + (p << 3);
            float s = 0.f;
#pragma unroll
            for (int q = 0; q < 8; ++q) {
                const float4 u = ar[q];
                s += u.x + u.y + u.z + u.w;
            }
            s += __shfl_down_sync(0xffffffffu, s, 1);
            s += __shfl_down_sync(0xffffffffu, s, 2);
            if (p == 0) {
                float rv = rsqrtf(s);
                rv = rv * (1.5f - 0.5f * s * rv * rv);  // Newton refine
                dinv[j] = rv;
            }
        }
        __syncthreads();

        // ---- A[r][c] *= dinv[r] * dinv[c] ----
        for (int idx = tid; idx < 4096; idx += BLK) {
            const int lin = idx << 2;
            const int r = lin >> 7, c4 = (lin & 127) >> 2;
            const float dr = dinv[r];
            const float4 dc = ((const float4*)dinv)[c4];
            float4 v = ((float4*)A)[idx];
            v.x *= dr * dc.x; v.y *= dr * dc.y;
            v.z *= dr * dc.z; v.w *= dr * dc.w;
            ((float4*)A)[idx] = v;
        }
        __syncthreads();

        // ---- X = relu(A @ Z) ----
        gemm128<true>(A, Z, X, tid);
        __syncthreads();
    }
}

extern "C" void kernel_launch(void* const* d_in, const int* in_sizes, int n_in,
                              void* d_out, int out_size)
{
    const float* x = (const float*)d_in[0];
    const float* W = (const float*)d_in[1];
    // defensive: identify W by size (128*128 = 16384) vs x (32*128*128 = 524288)
    if (n_in >= 2 && in_sizes[0] == 16384 && in_sizes[1] != 16384) {
        const float* t = x; x = W; W = t;
    }
    float* out = (float*)d_out;

    const size_t smem_bytes = (size_t)(3 * 16384 + 256) * sizeof(float);  // 197632
    cudaFuncSetAttribute(gcn_kernel, cudaFuncAttributeMaxDynamicSharedMemorySize,
                         (int)smem_bytes);
    gcn_kernel<<<32, BLK, smem_bytes>>>(x, W, out);
}

// round 3
// speedup vs baseline: 2.1114x; 2.1114x over previous
#include <cuda_runtime.h>
#include <cooperative_groups.h>
namespace cg = cooperative_groups;

#define NDIM 128
#define RPC  32          // rows per CTA (quarter)
#define BLK  512
#define CLUS 4

// shared-memory layout (float offsets)
#define OFF_W    0
#define OFF_Z    16384
#define OFF_A    32768          // 32x128 local quarter
#define OFF_X    36864          // 32x128 local quarter
#define OFF_XI   40960          // 128
#define OFF_PROB 41088          // 128
#define OFF_DINV 41216          // 128
#define SMEM_FLOATS 41344       // 165376 bytes

// ---------- packed f32x2 helpers ----------
__device__ __forceinline__ unsigned long long pack2(float v) {
    unsigned long long r;
    asm("mov.b64 %0, {%1, %1};" : "=l"(r) : "f"(v));
    return r;
}
__device__ __forceinline__ void fma2(unsigned long long& d, unsigned long long a, unsigned long long b) {
    asm("fma.rn.f32x2 %0, %1, %2, %0;" : "+l"(d) : "l"(a), "l"(b));
}
__device__ __forceinline__ float2 unpack2(unsigned long long v) {
    float2 r;
    asm("mov.b64 {%0, %1}, %2;" : "=f"(r.x), "=f"(r.y) : "l"(v));
    return r;
}
__device__ __forceinline__ float4 acc_to_f4(const unsigned long long a0,
                                            const unsigned long long a1, bool relu) {
    float2 lo = unpack2(a0), hi = unpack2(a1);
    float4 v = make_float4(lo.x, lo.y, hi.x, hi.y);
    if (relu) {
        v.x = fmaxf(v.x, 0.f); v.y = fmaxf(v.y, 0.f);
        v.z = fmaxf(v.z, 0.f); v.w = fmaxf(v.w, 0.f);
    }
    return v;
}

// ---------- 32x128x128 GEMM accumulate: each thread 2 rows x 4 cols ----------
// 512 threads = 16 row-groups (warps, broadcast A loads) x 32 col-groups.
__device__ __forceinline__ void gemm32_acc(const float* __restrict__ As,
                                           const float* __restrict__ Bs,
                                           int tid, unsigned long long acc[2][2])
{
    const int tc = (tid & 31) << 2;
    const int tr = (tid >> 5) << 1;
    acc[0][0] = acc[0][1] = acc[1][0] = acc[1][1] = 0ull;

#pragma unroll 2
    for (int k = 0; k < NDIM; k += 4) {
        const float4 a0 = *(const float4*)(As + tr * NDIM + k);
        const float4 a1 = *(const float4*)(As + (tr + 1) * NDIM + k);
#pragma unroll
        for (int kk = 0; kk < 4; ++kk) {
            const ulonglong2 bv = *(const ulonglong2*)(Bs + (k + kk) * NDIM + tc);
            const unsigned long long p0 = pack2(((const float*)&a0)[kk]);
            fma2(acc[0][0], p0, bv.x);
            fma2(acc[0][1], p0, bv.y);
            const unsigned long long p1 = pack2(((const float*)&a1)[kk]);
            fma2(acc[1][0], p1, bv.x);
            fma2(acc[1][1], p1, bv.y);
        }
    }
}

__global__ void __launch_bounds__(BLK, 1) __cluster_dims__(CLUS, 1, 1)
gcn_kernel(const float* __restrict__ xg, const float* __restrict__ Wg,
           float* __restrict__ outg)
{
    extern __shared__ float sm[];
    float* Ws   = sm + OFF_W;
    float* Z    = sm + OFF_Z;
    float* A    = sm + OFF_A;
    float* X    = sm + OFF_X;
    float* xi   = sm + OFF_XI;
    float* prob = sm + OFF_PROB;
    float* dinv = sm + OFF_DINV;

    cg::cluster_group cl = cg::this_cluster();
    const int rank  = (int)cl.block_rank();
    const int tid   = threadIdx.x;
    const int batch = blockIdx.x / CLUS;
    const int r0    = rank * RPC;

    float* peer[CLUS];
#pragma unroll
    for (int r = 0; r < CLUS; ++r) peer[r] = (float*)cl.map_shared_rank((void*)sm, r);

    const float* __restrict__ xb = xg + (size_t)batch * 16384 + (size_t)r0 * NDIM;
    float* __restrict__ ob = outg + (size_t)batch * 16384;

    // ---- prologue: W -> smem, local x quarter -> A (temp), out quarter = eye ----
    for (int idx = tid; idx < 4096; idx += BLK)
        ((float4*)Ws)[idx] = ((const float4*)Wg)[idx];
    for (int idx = tid; idx < 1024; idx += BLK)
        ((float4*)A)[idx] = ((const float4*)xb)[idx];
    for (int idx = tid; idx < 1024; idx += BLK) {
        const int lin = idx << 2;
        const int jg = r0 + (lin >> 7), c = lin & 127;
        float4 e = make_float4(0.f, 0.f, 0.f, 0.f);
        const int d = jg - c;
        if (d >= 0 && d < 4) ((float*)&e)[d] = 1.0f;
        ((float4*)(ob + (size_t)r0 * NDIM))[idx] = e;
    }
    __syncthreads();

    // X_local = relu(x_local @ W)
    {
        unsigned long long acc[2][2];
        gemm32_acc(A, Ws, tid, acc);
        const int tc = (tid & 31) << 2, tr = (tid >> 5) << 1;
        *(float4*)(X + tr * NDIM + tc)       = acc_to_f4(acc[0][0], acc[0][1], true);
        *(float4*)(X + (tr + 1) * NDIM + tc) = acc_to_f4(acc[1][0], acc[1][1], true);
    }
    __syncthreads();

    // A_local = eye quarter
    for (int idx = tid; idx < 1024; idx += BLK) {
        const int lin = idx << 2;
        const int jg = r0 + (lin >> 7), c = lin & 127;
        float4 e = make_float4(0.f, 0.f, 0.f, 0.f);
        const int d = jg - c;
        if (d >= 0 && d < 4) ((float*)&e)[d] = 1.0f;
        ((float4*)A)[idx] = e;
    }
    // broadcast X row 1 (owner: rank 0) for the first iteration
    if (rank == 0 && tid < 32) {
        const float4 v = ((const float4*)(X + 1 * NDIM))[tid];
#pragma unroll
        for (int r = 0; r < CLUS; ++r)
            ((float4*)(peer[r] + OFF_XI))[tid] = v;
    }
    cl.sync();

    for (int i = 1; i < NDIM; ++i) {
        // ---- prob[j] = dot(X_local[j], xi) for local j; broadcast to all ----
        {
            const int jl = tid >> 4, p = tid & 15;
            const float4* xj = (const float4*)(X + jl * NDIM) + (p << 1);
            const float4* xv = (const float4*)xi + (p << 1);
            float s = 0.f;
#pragma unroll
            for (int q = 0; q < 2; ++q) {
                const float4 u = xj[q], w = xv[q];
                s += u.x * w.x + u.y * w.y + u.z * w.z + u.w * w.w;
            }
            s += __shfl_down_sync(0xffffffffu, s, 8);
            s += __shfl_down_sync(0xffffffffu, s, 4);
            s += __shfl_down_sync(0xffffffffu, s, 2);
            s += __shfl_down_sync(0xffffffffu, s, 1);
            if (p == 0) {
                const int jg = r0 + jl;
#pragma unroll
                for (int r = 0; r < CLUS; ++r)
                    peer[r][OFF_PROB + jg] = s;
            }
        }

        // ---- Z quarter = X_local @ W, scattered to every CTA's full Z ----
        if (i < NDIM - 1) {
            unsigned long long acc[2][2];
            gemm32_acc(X, Ws, tid, acc);
            const int tc = (tid & 31) << 2, tr = (tid >> 5) << 1;
#pragma unroll
            for (int rr = 0; rr < 2; ++rr) {
                const float4 v = acc_to_f4(acc[rr][0], acc[rr][1], false);
                const int gofs = (r0 + tr + rr) * NDIM + tc;
#pragma unroll
                for (int r = 0; r < CLUS; ++r)
                    *(float4*)(peer[r] + OFF_Z + gofs) = v;
            }
        }
        cl.sync();   // prob (full) + Z (full) visible everywhere

        // ---- splice prob into A row/col i and the output ----
        if (tid < RPC) {
            const int jg = r0 + tid;
            if (jg < i) {
                const float pv = prob[jg];
                A[tid * NDIM + i] = pv;
                ob[(size_t)jg * NDIM + i] = pv;
            }
        }
        if (rank == (i >> 5) && tid < i) {
            const int il = i & 31;
            const float pv = prob[tid];
            A[il * NDIM + tid] = pv;
            ob[(size_t)i * NDIM + tid] = pv;
        }
        if (i == NDIM - 1) break;   // last step: only the splice matters for output
        __syncthreads();

        // ---- deg -> dinv (local rows), broadcast dinv ----
        {
            const int jl = tid >> 4, p = tid & 15;
            const float4* ar = (const float4*)(A + jl * NDIM) + (p << 1);
            float s = 0.f;
#pragma unroll
            for (int q = 0; q < 2; ++q) {
                const float4 u = ar[q];
                s += u.x + u.y + u.z + u.w;
            }
            s += __shfl_down_sync(0xffffffffu, s, 8);
            s += __shfl_down_sync(0xffffffffu, s, 4);
            s += __shfl_down_sync(0xffffffffu, s, 2);
            s += __shfl_down_sync(0xffffffffu, s, 1);
            if (p == 0) {
                float rv = rsqrtf(s);
                rv = rv * (1.5f - 0.5f * s * rv * rv);   // Newton refine
                const int jg = r0 + jl;
#pragma unroll
                for (int r = 0; r < CLUS; ++r)
                    peer[r][OFF_DINV + jg] = rv;
            }
        }
        cl.sync();   // dinv (full) visible

        // ---- A_local[r][c] *= dinv[r0+r] * dinv[c] ----
        for (int idx = tid; idx < 1024; idx += BLK) {
            const int lin = idx << 2;
            const int jr = lin >> 7, c4 = (lin & 127) >> 2;
            const float dr = dinv[r0 + jr];
            const float4 dc = ((const float4*)dinv)[c4];
            float4 v = ((float4*)A)[idx];
            v.x *= dr * dc.x; v.y *= dr * dc.y;
            v.z *= dr * dc.z; v.w *= dr * dc.w;
            ((float4*)A)[idx] = v;
        }
        __syncthreads();

        // ---- X_local = relu(A_local @ Z_full) ----
        {
            unsigned long long acc[2][2];
            gemm32_acc(A, Z, tid, acc);
            const int tc = (tid & 31) << 2, tr = (tid >> 5) << 1;
            *(float4*)(X + tr * NDIM + tc)       = acc_to_f4(acc[0][0], acc[0][1], true);
            *(float4*)(X + (tr + 1) * NDIM + tc) = acc_to_f4(acc[1][0], acc[1][1], true);
        }
        __syncthreads();

        // ---- broadcast X row (i+1) from its owner for the next step ----
        {
            const int ni = i + 1;
            if (rank == (ni >> 5) && tid < 32) {
                const float4 v = ((const float4*)(X + (ni & 31) * NDIM))[tid];
#pragma unroll
                for (int r = 0; r < CLUS; ++r)
                    ((float4*)(peer[r] + OFF_XI))[tid] = v;
            }
        }
        cl.sync();
    }
}

extern "C" void kernel_launch(void* const* d_in, const int* in_sizes, int n_in,
                              void* d_out, int out_size)
{
    const float* x = (const float*)d_in[0];
    const float* W = (const float*)d_in[1];
    if (n_in >= 2 && in_sizes[0] == 16384 && in_sizes[1] != 16384) {
        const float* t = x; x = W; W = t;
    }
    float* out = (float*)d_out;

    const size_t smem_bytes = (size_t)SMEM_FLOATS * sizeof(float);  // 165376
    cudaFuncSetAttribute(gcn_kernel, cudaFuncAttributeMaxDynamicSharedMemorySize,
                         (int)smem_bytes);
    gcn_kernel<<<32 * CLUS, BLK, smem_bytes>>>(x, W, out);
}